// round 14
// baseline (speedup 1.0000x reference)
#include <cuda_runtime.h>

namespace {

constexpr int G  = 8;    // group size
constexpr int L  = 50;   // history length
constexpr int S  = 32;   // social neighbors
constexpr int D  = 64;   // embed dim
constexpr int A  = 16;   // attention dim
constexpr int NR = 5;    // num ratings
constexpr int R  = 4;    // batch rows per CTA
constexpr int NT = 256;  // threads per CTA

constexpr int UMAX = 100352;   // >= NUM_USERS, padded

// per-user attention logit: tanh(features[u] @ wg1 + bg1) @ wg2  (bg2 cancels in softmax)
__device__ float g_logit[UMAX];

__device__ __forceinline__ bool mask_at(const void* m, long idx, int kind)
{
    if (kind == 1) return ((const int*)m)[idx] != 0;
    if (kind == 2) return ((const float*)m)[idx] != 0.f;
    return ((const unsigned char*)m)[idx] != 0;
}

__device__ __forceinline__ float fast_tanh(float x)
{
    float y;
    asm("tanh.approx.f32 %0, %1;" : "=f"(y) : "f"(x));
    return y;
}

// ---------------- kernel A: per-user logit precompute (verified R11/R12 version) ----------------
constexpr int UPB = 64;

__global__ __launch_bounds__(256)
void logit_kernel(const float* __restrict__ features,
                  const float* __restrict__ wg1,
                  const float* __restrict__ bg1,
                  const float* __restrict__ wg2,
                  int n_users)
{
    __shared__ __align__(16) float s_w[A][4][24];
    __shared__ float s_b[A], s_v[A];

    const int tid = threadIdx.x;
    const int u0  = blockIdx.x * UPB;

    for (int i = tid; i < D * A; i += 256) {
        int a = i >> 6, dd = i & 63;
        s_w[a][dd >> 4][dd & 15] = wg1[dd * A + a];
    }
    if (tid < A) { s_b[tid] = bg1[tid]; s_v[tid] = wg2[tid]; }
    __syncthreads();

    const int ul = tid >> 2;
    const int q  = tid & 3;
    const int u  = u0 + ul;

    float mem[16];
    {
        float4* mp = (float4*)mem;
        if (u < n_users) {
            const float4* f4 = (const float4*)features;
            #pragma unroll
            for (int i = 0; i < 4; ++i)
                mp[i] = f4[u * (D / 4) + q * 4 + i];
        } else {
            #pragma unroll
            for (int i = 0; i < 4; ++i)
                mp[i] = make_float4(0.f, 0.f, 0.f, 0.f);
        }
    }

    float logit = 0.f;
    #pragma unroll
    for (int a = 0; a < A; ++a) {
        float wv[16];
        {
            float4* wp = (float4*)wv;
            #pragma unroll
            for (int i = 0; i < 4; ++i)
                wp[i] = *(const float4*)&s_w[a][q][4 * i];
        }
        float acc = 0.f;
        #pragma unroll
        for (int i = 0; i < 16; ++i)
            acc += mem[i] * wv[i];
        acc += __shfl_xor_sync(0xffffffffu, acc, 1);
        acc += __shfl_xor_sync(0xffffffffu, acc, 2);
        logit += fast_tanh(acc + s_b[a]) * s_v[a];
    }
    if (q == 0 && u < n_users)
        g_logit[u] = logit;
}

// ---------------- kernel B: fused encoder — direct gathers, no compaction ----------------
__global__ __launch_bounds__(NT, 6)
void enc_kernel(const int* __restrict__ nodes,
                const int* __restrict__ hist_u,
                const int* __restrict__ hist_r,
                const void* __restrict__ hist_m,
                const int* __restrict__ soc_a,
                const void* __restrict__ soc_m,
                const float* __restrict__ features,
                const float* __restrict__ r_embed,
                const float* __restrict__ w1,
                const float* __restrict__ b1,
                float* __restrict__ out)
{
    __shared__ __align__(16) float4 s_mem4[R][G][D / 4];   // member embeddings (8 KB)
    __shared__ __align__(16) float  s_comb[R][2 * D];       // [self | neigh] (2 KB)
    __shared__ __align__(16) float4 s_red[8][R][D / 4];     // reduction scratch (8 KB)
    __shared__ float s_lg[R][G];
    __shared__ int   s_cnt[R][2][8];   // per-warp: [0]=hist cnt, [1..5]=rating cnts, [6]=soc cnt

    const int tid  = threadIdx.x;
    const int b0   = blockIdx.x * R;
    const int r    = tid >> 6;
    const int t    = tid & 63;
    const int lane = tid & 31;

    // ---------- P1a: per-warp mask dtype detection (no barrier) ----------
    int kind;
    {
        const unsigned* mw = (const unsigned*)hist_m;
        unsigned wa = mw[lane], wb = mw[lane + 32];
        bool ni = (wa > 1u) | (wb > 1u);
        bool nf = ((wa != 0u) & (wa != 0x3F800000u)) | ((wb != 0u) & (wb != 0x3F800000u));
        ni = __any_sync(0xffffffffu, ni);
        nf = __any_sync(0xffffffffu, nf);
        kind = !ni ? 1 : (!nf ? 2 : 0);
    }

    // ---------- P1b: member staging + member logits (independent loads, issue early) ----------
    for (int i = tid; i < R * G * (D / 4); i += NT) {
        int rr = i >> 7, g = (i >> 4) & 7, d4 = i & 15;
        int u = nodes[(b0 + rr) * G + g];
        s_mem4[rr][g][d4] = ((const float4*)features)[u * (D / 4) + d4];
    }
    if (tid >= 64 && tid < 64 + R * G) {
        int j  = tid - 64;
        int rr = j >> 3, g = j & 7;
        s_lg[rr][g] = g_logit[nodes[(b0 + rr) * G + g]];
    }

    // ---------- P1c: direct masked gathers (no compaction) ----------
    {
        const int e = t >> 4, d4 = t & 15;
        const float4* f4 = (const float4*)features;

        float4 ha = make_float4(0.f, 0.f, 0.f, 0.f);
        int hc = 0, c0 = 0, c1 = 0, c2 = 0, c3 = 0, c4 = 0;
        const long hbase = (long)(b0 + r) * L;
        #pragma unroll 4
        for (int l0 = 0; l0 < 52; l0 += 4) {
            int l = l0 + e;
            bool v = false; int u = 0, rt = 0;
            if (l < L) {
                long gi = hbase + l;
                v  = mask_at(hist_m, gi, kind);
                u  = hist_u[gi];
                rt = hist_r[gi];
            }
            if (v) {
                float4 fv = f4[u * (D / 4) + d4];
                ha.x += fv.x; ha.y += fv.y; ha.z += fv.z; ha.w += fv.w;
                hc++;
                c0 += (rt == 0); c1 += (rt == 1); c2 += (rt == 2);
                c3 += (rt == 3); c4 += (rt == 4);
            }
        }
        s_red[e][r][d4] = ha;

        float4 sa = make_float4(0.f, 0.f, 0.f, 0.f);
        int sc = 0;
        const long sbase = (long)(b0 + r) * S;
        #pragma unroll 4
        for (int l0 = 0; l0 < 32; l0 += 4) {
            long gi = sbase + l0 + e;
            bool v = mask_at(soc_m, gi, kind);
            int  u = soc_a[gi];
            if (v) {
                float4 fv = f4[u * (D / 4) + d4];
                sa.x += fv.x; sa.y += fv.y; sa.z += fv.z; sa.w += fv.w;
                sc++;
            }
        }
        s_red[4 + e][r][d4] = sa;

        // reduce counts across the warp's e-pair (lanes differ only in e via bit 4; d4 lanes redundant)
        hc += __shfl_xor_sync(0xffffffffu, hc, 16);
        sc += __shfl_xor_sync(0xffffffffu, sc, 16);
        c0 += __shfl_xor_sync(0xffffffffu, c0, 16);
        c1 += __shfl_xor_sync(0xffffffffu, c1, 16);
        c2 += __shfl_xor_sync(0xffffffffu, c2, 16);
        c3 += __shfl_xor_sync(0xffffffffu, c3, 16);
        c4 += __shfl_xor_sync(0xffffffffu, c4, 16);
        if (lane == 0) {
            const int w = (tid >> 5) & 1;
            s_cnt[r][w][0] = hc;
            s_cnt[r][w][1] = c0; s_cnt[r][w][2] = c1; s_cnt[r][w][3] = c2;
            s_cnt[r][w][4] = c3; s_cnt[r][w][5] = c4;
            s_cnt[r][w][6] = sc;
        }
    }
    __syncthreads();   // ===== sync1 =====

    // ---------- P2: softmax/self_feats ----------
    {
        const int d = t;
        float lgv[G];
        #pragma unroll
        for (int g = 0; g < G; ++g)
            lgv[g] = s_lg[r][g];
        float mx = lgv[0];
        #pragma unroll
        for (int g = 1; g < G; ++g) mx = fmaxf(mx, lgv[g]);
        float sum = 0.f;
        #pragma unroll
        for (int g = 0; g < G; ++g) { lgv[g] = __expf(lgv[g] - mx); sum += lgv[g]; }
        const float inv = 1.f / sum;
        float sf = 0.f;
        #pragma unroll
        for (int g = 0; g < G; ++g)
            sf += lgv[g] * ((const float*)&s_mem4[r][g][0])[d];
        s_comb[r][d] = sf * inv;
    }

    // ---------- P4: neighbor combine ----------
    {
        const int d = t;
        const float* rf = (const float*)s_red;
        float hs = 0.f, ss = 0.f;
        #pragma unroll
        for (int e = 0; e < 4; ++e) {
            hs += rf[((e)     * R + r) * D + d];
            ss += rf[((4 + e) * R + r) * D + d];
        }
        #pragma unroll
        for (int rt = 0; rt < NR; ++rt)
            hs += (float)(s_cnt[r][0][1 + rt] + s_cnt[r][1][1 + rt]) * r_embed[rt * D + d];
        const int hn = s_cnt[r][0][0] + s_cnt[r][1][0];
        const int sn = s_cnt[r][0][6] + s_cnt[r][1][6];
        float hmn = hs / fmaxf((float)hn, 1.f);
        float smn = ss / fmaxf((float)sn, 1.f);
        s_comb[r][D + d] = 0.5f * (hmn + smn);
    }
    __syncthreads();   // ===== sync2 =====

    // ---------- P5: final GEMM, k-split across 8 warps; half-warp = 2 rows ----------
    {
        const int w    = tid >> 5;           // k-slice: k in [16w, 16w+16)
        const int d4g  = lane & 15;
        const int rh   = lane >> 4;          // row-half: rows {2rh, 2rh+1}
        const float4* w1v = (const float4*)w1;
        float4 a0 = make_float4(0.f, 0.f, 0.f, 0.f);
        float4 a1 = make_float4(0.f, 0.f, 0.f, 0.f);
        #pragma unroll
        for (int j = 0; j < 4; ++j) {
            float c0a[4], c1a[4];
            *(float4*)c0a = *(const float4*)&s_comb[2 * rh][16 * w + 4 * j];
            *(float4*)c1a = *(const float4*)&s_comb[2 * rh + 1][16 * w + 4 * j];
            #pragma unroll
            for (int i = 0; i < 4; ++i) {
                const int k = 16 * w + 4 * j + i;
                float4 wv = w1v[k * (D / 4) + d4g];
                float c0 = c0a[i], c1 = c1a[i];
                a0.x += c0 * wv.x; a0.y += c0 * wv.y; a0.z += c0 * wv.z; a0.w += c0 * wv.w;
                a1.x += c1 * wv.x; a1.y += c1 * wv.y; a1.z += c1 * wv.z; a1.w += c1 * wv.w;
            }
        }
        s_red[w][2 * rh][d4g]     = a0;
        s_red[w][2 * rh + 1][d4g] = a1;
    }
    __syncthreads();   // ===== sync3 =====

    // ---------- P6: reduce over 8 k-slices + bias + relu + store ----------
    {
        const int d = t;
        const float* rf = (const float*)s_red;
        float o = b1[d];
        #pragma unroll
        for (int w2 = 0; w2 < 8; ++w2)
            o += rf[(w2 * R + r) * D + d];
        out[(long)(b0 + r) * D + d] = fmaxf(o, 0.f);
    }
}

} // namespace

extern "C" void kernel_launch(void* const* d_in, const int* in_sizes, int n_in,
                              void* d_out, int out_size)
{
    const int*   nodes    = (const int*)d_in[0];
    const int*   hist_u   = (const int*)d_in[1];
    const int*   hist_r   = (const int*)d_in[2];
    const void*  hist_m   = d_in[3];
    const int*   soc_a    = (const int*)d_in[4];
    const void*  soc_m    = d_in[5];
    const float* features = (const float*)d_in[6];
    const float* r_embed  = (const float*)d_in[7];
    const float* wg1      = (const float*)d_in[8];
    const float* bg1      = (const float*)d_in[9];
    const float* wg2      = (const float*)d_in[10];
    // d_in[11] = bg2: cancels inside softmax, unused
    const float* w1       = (const float*)d_in[12];
    const float* b1       = (const float*)d_in[13];
    float*       out      = (float*)d_out;

    const int B       = in_sizes[0] / G;
    const int n_users = in_sizes[6] / D;

    logit_kernel<<<(n_users + UPB - 1) / UPB, 256>>>(features, wg1, bg1, wg2, n_users);
    enc_kernel<<<B / R, NT>>>(nodes, hist_u, hist_r, hist_m, soc_a, soc_m,
                              features, r_embed, w1, b1, out);
}

// round 15
// speedup vs baseline: 1.3283x; 1.3283x over previous
#include <cuda_runtime.h>

namespace {

constexpr int G  = 8;    // group size
constexpr int L  = 50;   // history length
constexpr int S  = 32;   // social neighbors
constexpr int D  = 64;   // embed dim
constexpr int A  = 16;   // attention dim
constexpr int NR = 5;    // num ratings
constexpr int R  = 4;    // batch rows per CTA
constexpr int NT = 256;  // threads per CTA

constexpr int UMAX = 100352;   // >= NUM_USERS, padded

// per-user attention logit: tanh(features[u] @ wg1 + bg1) @ wg2  (bg2 cancels in softmax)
__device__ float g_logit[UMAX];

__device__ __forceinline__ bool mask_at(const void* m, long idx, int kind)
{
    if (kind == 1) return ((const int*)m)[idx] != 0;
    if (kind == 2) return ((const float*)m)[idx] != 0.f;
    return ((const unsigned char*)m)[idx] != 0;
}

__device__ __forceinline__ float fast_tanh(float x)
{
    float y;
    asm("tanh.approx.f32 %0, %1;" : "=f"(y) : "f"(x));
    return y;
}

// ---------------- kernel A: per-user logit precompute (verified R12 version + PDL trigger) ----------------
constexpr int UPB = 64;

__global__ __launch_bounds__(256)
void logit_kernel(const float* __restrict__ features,
                  const float* __restrict__ wg1,
                  const float* __restrict__ bg1,
                  const float* __restrict__ wg2,
                  int n_users)
{
    __shared__ __align__(16) float s_w[A][4][24];
    __shared__ float s_b[A], s_v[A];

    const int tid = threadIdx.x;
    const int u0  = blockIdx.x * UPB;

    for (int i = tid; i < D * A; i += 256) {
        int a = i >> 6, dd = i & 63;
        s_w[a][dd >> 4][dd & 15] = wg1[dd * A + a];
    }
    if (tid < A) { s_b[tid] = bg1[tid]; s_v[tid] = wg2[tid]; }
    __syncthreads();

    const int ul = tid >> 2;
    const int q  = tid & 3;
    const int u  = u0 + ul;

    float mem[16];
    {
        float4* mp = (float4*)mem;
        if (u < n_users) {
            const float4* f4 = (const float4*)features;
            #pragma unroll
            for (int i = 0; i < 4; ++i)
                mp[i] = f4[u * (D / 4) + q * 4 + i];
        } else {
            #pragma unroll
            for (int i = 0; i < 4; ++i)
                mp[i] = make_float4(0.f, 0.f, 0.f, 0.f);
        }
    }

    float logit = 0.f;
    #pragma unroll
    for (int a = 0; a < A; ++a) {
        float wv[16];
        {
            float4* wp = (float4*)wv;
            #pragma unroll
            for (int i = 0; i < 4; ++i)
                wp[i] = *(const float4*)&s_w[a][q][4 * i];
        }
        float acc = 0.f;
        #pragma unroll
        for (int i = 0; i < 16; ++i)
            acc += mem[i] * wv[i];
        acc += __shfl_xor_sync(0xffffffffu, acc, 1);
        acc += __shfl_xor_sync(0xffffffffu, acc, 2);
        logit += fast_tanh(acc + s_b[a]) * s_v[a];
    }
    if (q == 0 && u < n_users)
        g_logit[u] = logit;

    // PDL: our writes are done; allow dependents' griddepcontrol.wait to release
    asm volatile("griddepcontrol.launch_dependents;");
}

// ---------------- kernel B: fused encoder (R12 body, logit read moved behind griddepcontrol.wait) ----------------
__global__ __launch_bounds__(NT, 8)
void enc_kernel(const int* __restrict__ nodes,
                const int* __restrict__ hist_u,
                const int* __restrict__ hist_r,
                const void* __restrict__ hist_m,
                const int* __restrict__ soc_a,
                const void* __restrict__ soc_m,
                const float* __restrict__ features,
                const float* __restrict__ r_embed,
                const float* __restrict__ w1,
                const float* __restrict__ b1,
                float* __restrict__ out)
{
    __shared__ __align__(16) float4 s_mem4[R][G][D / 4];   // member embeddings (8 KB)
    __shared__ __align__(16) float  s_comb[R][2 * D];       // [self | neigh] (2 KB)
    __shared__ __align__(16) float4 s_red[8][R][D / 4];     // reduction scratch (8 KB)
    __shared__ float s_lg[R][G];
    __shared__ int   s_hu[R][L];
    __shared__ int   s_su[R][S];
    __shared__ int   s_wcnt[R][2];        // hist per-warp counts
    __shared__ int   s_sn[R];
    __shared__ int   s_rcnt2[R][2][NR];   // per-warp rating histograms

    const int tid  = threadIdx.x;
    const int b0   = blockIdx.x * R;
    const int r    = tid >> 6;
    const int t    = tid & 63;
    const int lane = tid & 31;
    const int hw   = (tid >> 5) & 1;      // hist warp within row

    // ---------- P1a: per-warp mask dtype detection (no barrier) ----------
    int kind;
    {
        const unsigned* mw = (const unsigned*)hist_m;
        unsigned wa = mw[lane], wb = mw[lane + 32];
        bool ni = (wa > 1u) | (wb > 1u);
        bool nf = ((wa != 0u) & (wa != 0x3F800000u)) | ((wb != 0u) & (wb != 0x3F800000u));
        ni = __any_sync(0xffffffffu, ni);
        nf = __any_sync(0xffffffffu, nf);
        kind = !ni ? 1 : (!nf ? 2 : 0);
    }

    // ---------- P1b: hist compaction (ballot, warp-local base) ----------
    {
        bool hm_v = false; int huv = 0, rtv = 0;
        if (t < L) {
            long gi = (long)(b0 + r) * L + t;
            hm_v = mask_at(hist_m, gi, kind);
            huv  = hist_u[gi];
            rtv  = hist_r[gi];
        }
        unsigned bal = __ballot_sync(0xffffffffu, hm_v);
        int hp = __popc(bal & ((1u << lane) - 1u));
        int base = 0;
        if (hw) {
            long gi0 = (long)(b0 + r) * L + lane;
            bool m0 = mask_at(hist_m, gi0, kind);
            base = __popc(__ballot_sync(0xffffffffu, m0));
        } else {
            __ballot_sync(0xffffffffu, false);
        }
        if (lane == 0) s_wcnt[r][hw] = __popc(bal);
        if (hm_v) s_hu[r][base + hp] = huv;
        #pragma unroll
        for (int q = 0; q < NR; ++q) {
            unsigned bq = __ballot_sync(0xffffffffu, hm_v && (rtv == q));
            if (lane == 0) s_rcnt2[r][hw][q] = __popc(bq);
        }
    }

    // ---------- P1c: social compaction ----------
    if (tid < R * S) {
        const int rr = tid >> 5;
        long gi = (long)(b0 + rr) * S + lane;
        bool m = mask_at(soc_m, gi, kind);
        int  u = soc_a[gi];
        unsigned bal = __ballot_sync(0xffffffffu, m);
        int p = __popc(bal & ((1u << lane) - 1u));
        if (m) s_su[rr][p] = u;
        if (lane == 0) s_sn[rr] = __popc(bal);
    }

    // ---------- P1d: member staging (independent of logit kernel) ----------
    for (int i = tid; i < R * G * (D / 4); i += NT) {
        int rr = i >> 7, g = (i >> 4) & 7, d4 = i & 15;
        int u = nodes[(b0 + rr) * G + g];
        s_mem4[rr][g][d4] = ((const float4*)features)[u * (D / 4) + d4];
    }
    __syncthreads();   // ===== sync1: compaction + members ready =====

    // ---------- P2: gathers (independent of logit kernel) ----------
    {
        const int e = t >> 4, d4 = t & 15;
        const float4* f4 = (const float4*)features;
        const int hn = s_wcnt[r][0] + s_wcnt[r][1];
        float4 ha = make_float4(0.f, 0.f, 0.f, 0.f);
        #pragma unroll 4
        for (int l = e; l < hn; l += 4) {
            int u = s_hu[r][l];
            float4 fv = f4[u * (D / 4) + d4];
            ha.x += fv.x; ha.y += fv.y; ha.z += fv.z; ha.w += fv.w;
        }
        s_red[e][r][d4] = ha;
        const int sn = s_sn[r];
        float4 sa = make_float4(0.f, 0.f, 0.f, 0.f);
        #pragma unroll 4
        for (int l = e; l < sn; l += 4) {
            int u = s_su[r][l];
            float4 fv = f4[u * (D / 4) + d4];
            sa.x += fv.x; sa.y += fv.y; sa.z += fv.z; sa.w += fv.w;
        }
        s_red[4 + e][r][d4] = sa;
    }

    // ---------- PDL sync: wait for logit kernel, then read member logits ----------
    asm volatile("griddepcontrol.wait;" ::: "memory");
    if (tid >= 64 && tid < 64 + R * G) {
        int j  = tid - 64;
        int rr = j >> 3, g = j & 7;
        s_lg[rr][g] = g_logit[nodes[(b0 + rr) * G + g]];
    }
    __syncthreads();   // ===== sync2: gathers + logits ready =====

    // ---------- P3: softmax/self_feats + neighbor combine ----------
    {
        const int d = t;
        float lgv[G];
        #pragma unroll
        for (int g = 0; g < G; ++g)
            lgv[g] = s_lg[r][g];
        float mx = lgv[0];
        #pragma unroll
        for (int g = 1; g < G; ++g) mx = fmaxf(mx, lgv[g]);
        float sum = 0.f;
        #pragma unroll
        for (int g = 0; g < G; ++g) { lgv[g] = __expf(lgv[g] - mx); sum += lgv[g]; }
        const float inv = 1.f / sum;
        float sf = 0.f;
        #pragma unroll
        for (int g = 0; g < G; ++g)
            sf += lgv[g] * ((const float*)&s_mem4[r][g][0])[d];
        s_comb[r][d] = sf * inv;
    }
    {
        const int d = t;
        const float* rf = (const float*)s_red;
        float hs = 0.f, ss = 0.f;
        #pragma unroll
        for (int e = 0; e < 4; ++e) {
            hs += rf[((e)     * R + r) * D + d];
            ss += rf[((4 + e) * R + r) * D + d];
        }
        #pragma unroll
        for (int rt = 0; rt < NR; ++rt)
            hs += (float)(s_rcnt2[r][0][rt] + s_rcnt2[r][1][rt]) * r_embed[rt * D + d];
        const int hn = s_wcnt[r][0] + s_wcnt[r][1];
        float hmn = hs / fmaxf((float)hn, 1.f);
        float smn = ss / fmaxf((float)s_sn[r], 1.f);
        s_comb[r][D + d] = 0.5f * (hmn + smn);
    }
    __syncthreads();   // ===== sync3 =====

    // ---------- P5: final GEMM, k-split across 8 warps; half-warp = 2 rows ----------
    {
        const int w    = tid >> 5;           // k-slice: k in [16w, 16w+16)
        const int d4g  = lane & 15;
        const int rh   = lane >> 4;          // row-half: rows {2rh, 2rh+1}
        const float4* w1v = (const float4*)w1;
        float4 a0 = make_float4(0.f, 0.f, 0.f, 0.f);
        float4 a1 = make_float4(0.f, 0.f, 0.f, 0.f);
        #pragma unroll
        for (int j = 0; j < 4; ++j) {
            float c0a[4], c1a[4];
            *(float4*)c0a = *(const float4*)&s_comb[2 * rh][16 * w + 4 * j];
            *(float4*)c1a = *(const float4*)&s_comb[2 * rh + 1][16 * w + 4 * j];
            #pragma unroll
            for (int i = 0; i < 4; ++i) {
                const int k = 16 * w + 4 * j + i;
                float4 wv = w1v[k * (D / 4) + d4g];
                float c0 = c0a[i], c1 = c1a[i];
                a0.x += c0 * wv.x; a0.y += c0 * wv.y; a0.z += c0 * wv.z; a0.w += c0 * wv.w;
                a1.x += c1 * wv.x; a1.y += c1 * wv.y; a1.z += c1 * wv.z; a1.w += c1 * wv.w;
            }
        }
        s_red[w][2 * rh][d4g]     = a0;
        s_red[w][2 * rh + 1][d4g] = a1;
    }
    __syncthreads();   // ===== sync4 =====

    // ---------- P6: reduce over 8 k-slices + bias + relu + store ----------
    {
        const int d = t;
        const float* rf = (const float*)s_red;
        float o = b1[d];
        #pragma unroll
        for (int w2 = 0; w2 < 8; ++w2)
            o += rf[(w2 * R + r) * D + d];
        out[(long)(b0 + r) * D + d] = fmaxf(o, 0.f);
    }
}

} // namespace

extern "C" void kernel_launch(void* const* d_in, const int* in_sizes, int n_in,
                              void* d_out, int out_size)
{
    const int*   nodes    = (const int*)d_in[0];
    const int*   hist_u   = (const int*)d_in[1];
    const int*   hist_r   = (const int*)d_in[2];
    const void*  hist_m   = d_in[3];
    const int*   soc_a    = (const int*)d_in[4];
    const void*  soc_m    = d_in[5];
    const float* features = (const float*)d_in[6];
    const float* r_embed  = (const float*)d_in[7];
    const float* wg1      = (const float*)d_in[8];
    const float* bg1      = (const float*)d_in[9];
    const float* wg2      = (const float*)d_in[10];
    // d_in[11] = bg2: cancels inside softmax, unused
    const float* w1       = (const float*)d_in[12];
    const float* b1       = (const float*)d_in[13];
    float*       out      = (float*)d_out;

    const int B       = in_sizes[0] / G;
    const int n_users = in_sizes[6] / D;

    logit_kernel<<<(n_users + UPB - 1) / UPB, 256>>>(features, wg1, bg1, wg2, n_users);

    // enc with programmatic dependent launch: CTAs may start while logit_kernel
    // is still running; griddepcontrol.wait in the kernel orders the g_logit read.
    {
        cudaLaunchConfig_t cfg = {};
        cfg.gridDim  = dim3(B / R, 1, 1);
        cfg.blockDim = dim3(NT, 1, 1);
        cfg.stream   = 0;
        cudaLaunchAttribute attrs[1];
        attrs[0].id = cudaLaunchAttributeProgrammaticStreamSerialization;
        attrs[0].val.programmaticStreamSerializationAllowed = 1;
        cfg.attrs    = attrs;
        cfg.numAttrs = 1;
        cudaLaunchKernelEx(&cfg, enc_kernel,
                           nodes, hist_u, hist_r, hist_m, soc_a, soc_m,
                           features, r_embed, w1, b1, out);
    }
}

// round 16
// speedup vs baseline: 1.4771x; 1.1120x over previous
#include <cuda_runtime.h>

namespace {

constexpr int G  = 8;    // group size
constexpr int L  = 50;   // history length
constexpr int S  = 32;   // social neighbors
constexpr int D  = 64;   // embed dim
constexpr int A  = 16;   // attention dim
constexpr int NR = 5;    // num ratings
constexpr int R  = 4;    // batch rows per CTA
constexpr int NT = 256;  // threads per CTA

constexpr int UMAX = 100352;   // >= NUM_USERS, padded

// per-user attention logit: tanh(features[u] @ wg1 + bg1) @ wg2  (bg2 cancels in softmax)
__device__ float g_logit[UMAX];

__device__ __forceinline__ bool mask_at(const void* m, long idx, int kind)
{
    if (kind == 1) return ((const int*)m)[idx] != 0;
    if (kind == 2) return ((const float*)m)[idx] != 0.f;
    return ((const unsigned char*)m)[idx] != 0;
}

__device__ __forceinline__ float fast_tanh(float x)
{
    float y;
    asm("tanh.approx.f32 %0, %1;" : "=f"(y) : "f"(x));
    return y;
}

// ---------------- kernel A: per-user logit, thread-per-user (no shuffles) ----------------
constexpr int UPB = 128;

__global__ __launch_bounds__(UPB)
void logit_kernel(const float* __restrict__ features,
                  const float* __restrict__ wg1,
                  const float* __restrict__ bg1,
                  const float* __restrict__ wg2,
                  int n_users)
{
    __shared__ __align__(16) float4 s_f[UPB][17];    // user rows, padded (34.8 KB)
    __shared__ __align__(16) float4 s_wa[A][16];      // per-a weight columns
    __shared__ float s_b[A], s_v[A];

    const int tid = threadIdx.x;
    const int u0  = blockIdx.x * UPB;
    const int nv  = (n_users - u0 < UPB) ? (n_users - u0) : UPB;

    // coalesced feature staging: consecutive threads -> consecutive float4
    {
        const float4* f4 = (const float4*)features + (long)u0 * (D / 4);
        for (int i = tid; i < nv * (D / 4); i += UPB)
            s_f[i >> 4][i & 15] = f4[i];
    }
    // weight staging: s_wa[a][d4] = {wg1[4d4+e][a]}e
    for (int i = tid; i < D * A; i += UPB) {
        int a = i >> 6, dd = i & 63;
        ((float*)&s_wa[a][dd >> 2])[dd & 3] = wg1[dd * A + a];
    }
    if (tid < A) { s_b[tid] = bg1[tid]; s_v[tid] = wg2[tid]; }
    __syncthreads();

    if (tid >= nv) {
        asm volatile("griddepcontrol.launch_dependents;");
        return;
    }

    // pull this user's row into registers (4-cyc crossbar floor per LDS.128)
    float4 fr[16];
    #pragma unroll
    for (int i = 0; i < 16; ++i)
        fr[i] = s_f[tid][i];

    float logit = 0.f;
    #pragma unroll
    for (int a = 0; a < A; ++a) {
        float acc = 0.f;
        #pragma unroll
        for (int d4 = 0; d4 < 16; ++d4) {
            float4 wv = s_wa[a][d4];   // warp-broadcast LDS
            acc += fr[d4].x * wv.x + fr[d4].y * wv.y
                 + fr[d4].z * wv.z + fr[d4].w * wv.w;
        }
        logit += fast_tanh(acc + s_b[a]) * s_v[a];
    }
    g_logit[u0 + tid] = logit;   // coalesced

    asm volatile("griddepcontrol.launch_dependents;");
}

// ---------------- kernel B: fused encoder (R15 body, unchanged) ----------------
__global__ __launch_bounds__(NT, 8)
void enc_kernel(const int* __restrict__ nodes,
                const int* __restrict__ hist_u,
                const int* __restrict__ hist_r,
                const void* __restrict__ hist_m,
                const int* __restrict__ soc_a,
                const void* __restrict__ soc_m,
                const float* __restrict__ features,
                const float* __restrict__ r_embed,
                const float* __restrict__ w1,
                const float* __restrict__ b1,
                float* __restrict__ out)
{
    __shared__ __align__(16) float4 s_mem4[R][G][D / 4];   // member embeddings (8 KB)
    __shared__ __align__(16) float  s_comb[R][2 * D];       // [self | neigh] (2 KB)
    __shared__ __align__(16) float4 s_red[8][R][D / 4];     // reduction scratch (8 KB)
    __shared__ float s_lg[R][G];
    __shared__ int   s_hu[R][L];
    __shared__ int   s_su[R][S];
    __shared__ int   s_wcnt[R][2];        // hist per-warp counts
    __shared__ int   s_sn[R];
    __shared__ int   s_rcnt2[R][2][NR];   // per-warp rating histograms

    const int tid  = threadIdx.x;
    const int b0   = blockIdx.x * R;
    const int r    = tid >> 6;
    const int t    = tid & 63;
    const int lane = tid & 31;
    const int hw   = (tid >> 5) & 1;      // hist warp within row

    // ---------- P1a: per-warp mask dtype detection (no barrier) ----------
    int kind;
    {
        const unsigned* mw = (const unsigned*)hist_m;
        unsigned wa = mw[lane], wb = mw[lane + 32];
        bool ni = (wa > 1u) | (wb > 1u);
        bool nf = ((wa != 0u) & (wa != 0x3F800000u)) | ((wb != 0u) & (wb != 0x3F800000u));
        ni = __any_sync(0xffffffffu, ni);
        nf = __any_sync(0xffffffffu, nf);
        kind = !ni ? 1 : (!nf ? 2 : 0);
    }

    // ---------- P1b: hist compaction (ballot, warp-local base) ----------
    {
        bool hm_v = false; int huv = 0, rtv = 0;
        if (t < L) {
            long gi = (long)(b0 + r) * L + t;
            hm_v = mask_at(hist_m, gi, kind);
            huv  = hist_u[gi];
            rtv  = hist_r[gi];
        }
        unsigned bal = __ballot_sync(0xffffffffu, hm_v);
        int hp = __popc(bal & ((1u << lane) - 1u));
        int base = 0;
        if (hw) {
            long gi0 = (long)(b0 + r) * L + lane;
            bool m0 = mask_at(hist_m, gi0, kind);
            base = __popc(__ballot_sync(0xffffffffu, m0));
        } else {
            __ballot_sync(0xffffffffu, false);
        }
        if (lane == 0) s_wcnt[r][hw] = __popc(bal);
        if (hm_v) s_hu[r][base + hp] = huv;
        #pragma unroll
        for (int q = 0; q < NR; ++q) {
            unsigned bq = __ballot_sync(0xffffffffu, hm_v && (rtv == q));
            if (lane == 0) s_rcnt2[r][hw][q] = __popc(bq);
        }
    }

    // ---------- P1c: social compaction ----------
    if (tid < R * S) {
        const int rr = tid >> 5;
        long gi = (long)(b0 + rr) * S + lane;
        bool m = mask_at(soc_m, gi, kind);
        int  u = soc_a[gi];
        unsigned bal = __ballot_sync(0xffffffffu, m);
        int p = __popc(bal & ((1u << lane) - 1u));
        if (m) s_su[rr][p] = u;
        if (lane == 0) s_sn[rr] = __popc(bal);
    }

    // ---------- P1d: member staging (independent of logit kernel) ----------
    for (int i = tid; i < R * G * (D / 4); i += NT) {
        int rr = i >> 7, g = (i >> 4) & 7, d4 = i & 15;
        int u = nodes[(b0 + rr) * G + g];
        s_mem4[rr][g][d4] = ((const float4*)features)[u * (D / 4) + d4];
    }
    __syncthreads();   // ===== sync1: compaction + members ready =====

    // ---------- P2: gathers (independent of logit kernel) ----------
    {
        const int e = t >> 4, d4 = t & 15;
        const float4* f4 = (const float4*)features;
        const int hn = s_wcnt[r][0] + s_wcnt[r][1];
        float4 ha = make_float4(0.f, 0.f, 0.f, 0.f);
        #pragma unroll 4
        for (int l = e; l < hn; l += 4) {
            int u = s_hu[r][l];
            float4 fv = f4[u * (D / 4) + d4];
            ha.x += fv.x; ha.y += fv.y; ha.z += fv.z; ha.w += fv.w;
        }
        s_red[e][r][d4] = ha;
        const int sn = s_sn[r];
        float4 sa = make_float4(0.f, 0.f, 0.f, 0.f);
        #pragma unroll 4
        for (int l = e; l < sn; l += 4) {
            int u = s_su[r][l];
            float4 fv = f4[u * (D / 4) + d4];
            sa.x += fv.x; sa.y += fv.y; sa.z += fv.z; sa.w += fv.w;
        }
        s_red[4 + e][r][d4] = sa;
    }

    // ---------- PDL sync: wait for logit kernel, then read member logits ----------
    asm volatile("griddepcontrol.wait;" ::: "memory");
    if (tid >= 64 && tid < 64 + R * G) {
        int j  = tid - 64;
        int rr = j >> 3, g = j & 7;
        s_lg[rr][g] = g_logit[nodes[(b0 + rr) * G + g]];
    }
    __syncthreads();   // ===== sync2: gathers + logits ready =====

    // ---------- P3: softmax/self_feats + neighbor combine ----------
    {
        const int d = t;
        float lgv[G];
        #pragma unroll
        for (int g = 0; g < G; ++g)
            lgv[g] = s_lg[r][g];
        float mx = lgv[0];
        #pragma unroll
        for (int g = 1; g < G; ++g) mx = fmaxf(mx, lgv[g]);
        float sum = 0.f;
        #pragma unroll
        for (int g = 0; g < G; ++g) { lgv[g] = __expf(lgv[g] - mx); sum += lgv[g]; }
        const float inv = 1.f / sum;
        float sf = 0.f;
        #pragma unroll
        for (int g = 0; g < G; ++g)
            sf += lgv[g] * ((const float*)&s_mem4[r][g][0])[d];
        s_comb[r][d] = sf * inv;
    }
    {
        const int d = t;
        const float* rf = (const float*)s_red;
        float hs = 0.f, ss = 0.f;
        #pragma unroll
        for (int e = 0; e < 4; ++e) {
            hs += rf[((e)     * R + r) * D + d];
            ss += rf[((4 + e) * R + r) * D + d];
        }
        #pragma unroll
        for (int rt = 0; rt < NR; ++rt)
            hs += (float)(s_rcnt2[r][0][rt] + s_rcnt2[r][1][rt]) * r_embed[rt * D + d];
        const int hn = s_wcnt[r][0] + s_wcnt[r][1];
        float hmn = hs / fmaxf((float)hn, 1.f);
        float smn = ss / fmaxf((float)s_sn[r], 1.f);
        s_comb[r][D + d] = 0.5f * (hmn + smn);
    }
    __syncthreads();   // ===== sync3 =====

    // ---------- P5: final GEMM, k-split across 8 warps; half-warp = 2 rows ----------
    {
        const int w    = tid >> 5;           // k-slice: k in [16w, 16w+16)
        const int d4g  = lane & 15;
        const int rh   = lane >> 4;          // row-half: rows {2rh, 2rh+1}
        const float4* w1v = (const float4*)w1;
        float4 a0 = make_float4(0.f, 0.f, 0.f, 0.f);
        float4 a1 = make_float4(0.f, 0.f, 0.f, 0.f);
        #pragma unroll
        for (int j = 0; j < 4; ++j) {
            float c0a[4], c1a[4];
            *(float4*)c0a = *(const float4*)&s_comb[2 * rh][16 * w + 4 * j];
            *(float4*)c1a = *(const float4*)&s_comb[2 * rh + 1][16 * w + 4 * j];
            #pragma unroll
            for (int i = 0; i < 4; ++i) {
                const int k = 16 * w + 4 * j + i;
                float4 wv = w1v[k * (D / 4) + d4g];
                float c0 = c0a[i], c1 = c1a[i];
                a0.x += c0 * wv.x; a0.y += c0 * wv.y; a0.z += c0 * wv.z; a0.w += c0 * wv.w;
                a1.x += c1 * wv.x; a1.y += c1 * wv.y; a1.z += c1 * wv.z; a1.w += c1 * wv.w;
            }
        }
        s_red[w][2 * rh][d4g]     = a0;
        s_red[w][2 * rh + 1][d4g] = a1;
    }
    __syncthreads();   // ===== sync4 =====

    // ---------- P6: reduce over 8 k-slices + bias + relu + store ----------
    {
        const int d = t;
        const float* rf = (const float*)s_red;
        float o = b1[d];
        #pragma unroll
        for (int w2 = 0; w2 < 8; ++w2)
            o += rf[(w2 * R + r) * D + d];
        out[(long)(b0 + r) * D + d] = fmaxf(o, 0.f);
    }
}

} // namespace

extern "C" void kernel_launch(void* const* d_in, const int* in_sizes, int n_in,
                              void* d_out, int out_size)
{
    const int*   nodes    = (const int*)d_in[0];
    const int*   hist_u   = (const int*)d_in[1];
    const int*   hist_r   = (const int*)d_in[2];
    const void*  hist_m   = d_in[3];
    const int*   soc_a    = (const int*)d_in[4];
    const void*  soc_m    = d_in[5];
    const float* features = (const float*)d_in[6];
    const float* r_embed  = (const float*)d_in[7];
    const float* wg1      = (const float*)d_in[8];
    const float* bg1      = (const float*)d_in[9];
    const float* wg2      = (const float*)d_in[10];
    // d_in[11] = bg2: cancels inside softmax, unused
    const float* w1       = (const float*)d_in[12];
    const float* b1       = (const float*)d_in[13];
    float*       out      = (float*)d_out;

    const int B       = in_sizes[0] / G;
    const int n_users = in_sizes[6] / D;

    logit_kernel<<<(n_users + UPB - 1) / UPB, UPB>>>(features, wg1, bg1, wg2, n_users);

    // enc with programmatic dependent launch: CTAs may start while logit_kernel
    // is still running; griddepcontrol.wait in the kernel orders the g_logit read.
    {
        cudaLaunchConfig_t cfg = {};
        cfg.gridDim  = dim3(B / R, 1, 1);
        cfg.blockDim = dim3(NT, 1, 1);
        cfg.stream   = 0;
        cudaLaunchAttribute attrs[1];
        attrs[0].id = cudaLaunchAttributeProgrammaticStreamSerialization;
        attrs[0].val.programmaticStreamSerializationAllowed = 1;
        cfg.attrs    = attrs;
        cfg.numAttrs = 1;
        cudaLaunchKernelEx(&cfg, enc_kernel,
                           nodes, hist_u, hist_r, hist_m, soc_a, soc_m,
                           features, r_embed, w1, b1, out);
    }
}